// round 1
// baseline (speedup 1.0000x reference)
#include <cuda_runtime.h>
#include <stdint.h>

#define BATCH   4
#define SEQ     2048
#define DMODEL  1024
#define NHEADS  16
#define HDIM    64
#define MTOT    (BATCH*SEQ)          // 8192

// ---------------- scratch (static device globals; no runtime allocation) ---
__device__ __align__(16) float g_q[(size_t)BATCH*NHEADS*SEQ*HDIM];
__device__ __align__(16) float g_k[(size_t)BATCH*NHEADS*SEQ*HDIM];
__device__ __align__(16) float g_v[(size_t)BATCH*NHEADS*SEQ*HDIM];
__device__ __align__(16) float g_attn[(size_t)MTOT*DMODEL];

// ---------------- helpers ---------------------------------------------------
__device__ __forceinline__ float f2tf32(float x) {
    uint32_t u;
    asm("cvt.rna.tf32.f32 %0, %1;" : "=r"(u) : "f"(x));
    return __uint_as_float(u);
}

// D += A*B, m16n8k8 tf32
__device__ __forceinline__ void mma8(float* c, const float* a, const float* b) {
    const uint32_t* A = reinterpret_cast<const uint32_t*>(a);
    const uint32_t* B = reinterpret_cast<const uint32_t*>(b);
    asm volatile(
        "mma.sync.aligned.m16n8k8.row.col.f32.tf32.tf32.f32 "
        "{%0,%1,%2,%3}, {%4,%5,%6,%7}, {%8,%9}, {%0,%1,%2,%3};\n"
        : "+f"(c[0]), "+f"(c[1]), "+f"(c[2]), "+f"(c[3])
        : "r"(A[0]), "r"(A[1]), "r"(A[2]), "r"(A[3]), "r"(B[0]), "r"(B[1]));
}

// ============================================================================
// GEMM (3xTF32 split, near-fp32 accuracy): C[M,N] = A[M,K] @ B[K,N]
// 128x128 tile, BK=32, 256 threads, warps 4(m) x 2(n), warp tile 32x64.
// EPI=0: plain row-major store to C. EPI=1: scatter qkv -> g_q/g_k/g_v.
// ============================================================================
#define APAD 36
#define BPAD 136
#define GEMM_SMEM_BYTES ((2*128*APAD + 2*32*BPAD)*4)   // 71680

template <int EPI>
__global__ void __launch_bounds__(256)
gemm3x(const float* __restrict__ A, const float* __restrict__ Bm,
       float* __restrict__ C, int M, int N, int K)
{
    extern __shared__ float sm[];
    float* AsH = sm;
    float* AsL = AsH + 128*APAD;
    float* BsH = AsL + 128*APAD;
    float* BsL = BsH + 32*BPAD;

    const int tid  = threadIdx.x;
    const int lane = tid & 31, warp = tid >> 5;
    const int wm = warp & 3, wn = warp >> 2;            // 4 x 2 warp grid
    const int g  = lane >> 2, tg = lane & 3;
    const int m0 = blockIdx.y * 128, n0 = blockIdx.x * 128;

    float acc[2][8][4];
    #pragma unroll
    for (int i = 0; i < 2; i++)
        #pragma unroll
        for (int j = 0; j < 8; j++)
            #pragma unroll
            for (int e = 0; e < 4; e++) acc[i][j][e] = 0.f;

    for (int k0 = 0; k0 < K; k0 += 32) {
        // load A tile 128x32 (1024 float4)
        #pragma unroll
        for (int j = 0; j < 4; j++) {
            int i  = tid + j*256;
            int r  = i >> 3, c4 = (i & 7) * 4;
            float4 v = *reinterpret_cast<const float4*>(A + (size_t)(m0+r)*K + k0 + c4);
            float h;
            h = f2tf32(v.x); AsH[r*APAD+c4+0] = h; AsL[r*APAD+c4+0] = f2tf32(v.x - h);
            h = f2tf32(v.y); AsH[r*APAD+c4+1] = h; AsL[r*APAD+c4+1] = f2tf32(v.y - h);
            h = f2tf32(v.z); AsH[r*APAD+c4+2] = h; AsL[r*APAD+c4+2] = f2tf32(v.z - h);
            h = f2tf32(v.w); AsH[r*APAD+c4+3] = h; AsL[r*APAD+c4+3] = f2tf32(v.w - h);
        }
        // load B tile 32x128 (1024 float4)
        #pragma unroll
        for (int j = 0; j < 4; j++) {
            int i  = tid + j*256;
            int r  = i >> 5, c4 = (i & 31) * 4;
            float4 v = *reinterpret_cast<const float4*>(Bm + (size_t)(k0+r)*N + n0 + c4);
            float h;
            h = f2tf32(v.x); BsH[r*BPAD+c4+0] = h; BsL[r*BPAD+c4+0] = f2tf32(v.x - h);
            h = f2tf32(v.y); BsH[r*BPAD+c4+1] = h; BsL[r*BPAD+c4+1] = f2tf32(v.y - h);
            h = f2tf32(v.z); BsH[r*BPAD+c4+2] = h; BsL[r*BPAD+c4+2] = f2tf32(v.z - h);
            h = f2tf32(v.w); BsH[r*BPAD+c4+3] = h; BsL[r*BPAD+c4+3] = f2tf32(v.w - h);
        }
        __syncthreads();

        #pragma unroll
        for (int ks = 0; ks < 4; ks++) {
            const int kc = ks*8;
            float afH[2][4], afL[2][4];
            #pragma unroll
            for (int mt = 0; mt < 2; mt++) {
                int rb = wm*32 + mt*16;
                afH[mt][0] = AsH[(rb+g  )*APAD + kc + tg  ];
                afH[mt][1] = AsH[(rb+g+8)*APAD + kc + tg  ];
                afH[mt][2] = AsH[(rb+g  )*APAD + kc + tg+4];
                afH[mt][3] = AsH[(rb+g+8)*APAD + kc + tg+4];
                afL[mt][0] = AsL[(rb+g  )*APAD + kc + tg  ];
                afL[mt][1] = AsL[(rb+g+8)*APAD + kc + tg  ];
                afL[mt][2] = AsL[(rb+g  )*APAD + kc + tg+4];
                afL[mt][3] = AsL[(rb+g+8)*APAD + kc + tg+4];
            }
            #pragma unroll
            for (int nt = 0; nt < 8; nt++) {
                int cb = wn*64 + nt*8;
                float bfH[2], bfL[2];
                bfH[0] = BsH[(kc+tg  )*BPAD + cb + g];
                bfH[1] = BsH[(kc+tg+4)*BPAD + cb + g];
                bfL[0] = BsL[(kc+tg  )*BPAD + cb + g];
                bfL[1] = BsL[(kc+tg+4)*BPAD + cb + g];
                #pragma unroll
                for (int mt = 0; mt < 2; mt++) {
                    mma8(acc[mt][nt], afH[mt], bfH);   // hi*hi
                    mma8(acc[mt][nt], afL[mt], bfH);   // lo*hi
                    mma8(acc[mt][nt], afH[mt], bfL);   // hi*lo
                }
            }
        }
        __syncthreads();
    }

    // epilogue
    #pragma unroll
    for (int mt = 0; mt < 2; mt++) {
        #pragma unroll
        for (int nt = 0; nt < 8; nt++) {
            #pragma unroll
            for (int e = 0; e < 4; e++) {
                int r = m0 + wm*32 + mt*16 + g + ((e >> 1) ? 8 : 0);
                int c = n0 + wn*64 + nt*8 + 2*tg + (e & 1);
                float v = acc[mt][nt][e];
                if (EPI == 0) {
                    C[(size_t)r*N + c] = v;
                } else {
                    int b = r >> 11, s = r & (SEQ-1);
                    int which = c >> 10, rem = c & (DMODEL-1);
                    int h = rem >> 6, d = rem & (HDIM-1);
                    float* dst = (which == 0) ? g_q : (which == 1) ? g_k : g_v;
                    dst[((size_t)((b*NHEADS + h)*SEQ + s))*HDIM + d] = v;
                }
            }
        }
    }
}

// ============================================================================
// Flash attention (tf32 mma): grid (S/128, B*H), 256 threads (8 warps).
// Each CTA: 128 q-rows; loop over 64-row K/V tiles; each warp owns 16 q-rows
// so softmax reductions are 4-lane shuffles. P goes through smem (tf32) to
// re-fragment for the PV mma.
// ============================================================================
#define SPAD 76
#define ATTN_SMEM_BYTES ((128*SPAD + 64*SPAD + 64*SPAD + 128*SPAD)*4)  // 116736

__global__ void __launch_bounds__(256)
flashattn()
{
    extern __shared__ float sm[];
    float* Qs = sm;                   // 128 x SPAD
    float* Ks = Qs + 128*SPAD;        // 64 x SPAD
    float* Vs = Ks + 64*SPAD;         // 64 x SPAD
    float* Ps = Vs + 64*SPAD;         // 128 x SPAD

    const int tid  = threadIdx.x;
    const int lane = tid & 31, warp = tid >> 5;
    const int g  = lane >> 2, tg = lane & 3;
    const int bh = blockIdx.y;                 // (b*NHEADS + h)
    const int q0 = blockIdx.x * 128;
    const int rb = warp * 16;                  // warp's q-row base inside tile
    const size_t hbase = (size_t)bh * SEQ * HDIM;
    const float scale = 0.125f;                // 1/sqrt(64)

    // load Q tile (scaled, tf32-rounded): 128x64 = 2048 float4
    #pragma unroll
    for (int j = 0; j < 8; j++) {
        int i  = tid + j*256;
        int r  = i >> 4, c4 = (i & 15) * 4;
        float4 v = *reinterpret_cast<const float4*>(g_q + hbase + (size_t)(q0+r)*HDIM + c4);
        Qs[r*SPAD+c4+0] = f2tf32(v.x * scale);
        Qs[r*SPAD+c4+1] = f2tf32(v.y * scale);
        Qs[r*SPAD+c4+2] = f2tf32(v.z * scale);
        Qs[r*SPAD+c4+3] = f2tf32(v.w * scale);
    }

    float m0v = -1e30f, m1v = -1e30f;   // running row max (rows g, g+8)
    float l0 = 0.f, l1 = 0.f;           // running row sum
    float o[8][4];
    #pragma unroll
    for (int nt = 0; nt < 8; nt++)
        #pragma unroll
        for (int e = 0; e < 4; e++) o[nt][e] = 0.f;

    for (int kt = 0; kt < SEQ/64; kt++) {
        __syncthreads();   // previous iteration done reading Ks/Vs (+ Q visible)
        // load K,V tiles: 64x64 each, 1024 float4 each
        #pragma unroll
        for (int j = 0; j < 4; j++) {
            int i  = tid + j*256;
            int r  = i >> 4, c4 = (i & 15) * 4;
            size_t off = hbase + (size_t)(kt*64 + r)*HDIM + c4;
            float4 kv = *reinterpret_cast<const float4*>(g_k + off);
            Ks[r*SPAD+c4+0] = f2tf32(kv.x);
            Ks[r*SPAD+c4+1] = f2tf32(kv.y);
            Ks[r*SPAD+c4+2] = f2tf32(kv.z);
            Ks[r*SPAD+c4+3] = f2tf32(kv.w);
            float4 vv = *reinterpret_cast<const float4*>(g_v + off);
            Vs[r*SPAD+c4+0] = f2tf32(vv.x);
            Vs[r*SPAD+c4+1] = f2tf32(vv.y);
            Vs[r*SPAD+c4+2] = f2tf32(vv.z);
            Vs[r*SPAD+c4+3] = f2tf32(vv.w);
        }
        __syncthreads();

        // S = Q @ K^T : warp computes 16 x 64
        float sacc[8][4];
        #pragma unroll
        for (int nt = 0; nt < 8; nt++)
            #pragma unroll
            for (int e = 0; e < 4; e++) sacc[nt][e] = 0.f;

        #pragma unroll
        for (int ks = 0; ks < 8; ks++) {
            const int kc = ks*8;
            float af[4];
            af[0] = Qs[(rb+g  )*SPAD + kc + tg  ];
            af[1] = Qs[(rb+g+8)*SPAD + kc + tg  ];
            af[2] = Qs[(rb+g  )*SPAD + kc + tg+4];
            af[3] = Qs[(rb+g+8)*SPAD + kc + tg+4];
            #pragma unroll
            for (int nt = 0; nt < 8; nt++) {
                float bf[2];
                bf[0] = Ks[(nt*8+g)*SPAD + kc + tg  ];
                bf[1] = Ks[(nt*8+g)*SPAD + kc + tg+4];
                mma8(sacc[nt], af, bf);
            }
        }

        // online softmax (rows g and g+8 of this warp's 16-row block)
        float mx0 = -1e30f, mx1 = -1e30f;
        #pragma unroll
        for (int nt = 0; nt < 8; nt++) {
            mx0 = fmaxf(mx0, fmaxf(sacc[nt][0], sacc[nt][1]));
            mx1 = fmaxf(mx1, fmaxf(sacc[nt][2], sacc[nt][3]));
        }
        mx0 = fmaxf(mx0, __shfl_xor_sync(0xffffffffu, mx0, 1));
        mx0 = fmaxf(mx0, __shfl_xor_sync(0xffffffffu, mx0, 2));
        mx1 = fmaxf(mx1, __shfl_xor_sync(0xffffffffu, mx1, 1));
        mx1 = fmaxf(mx1, __shfl_xor_sync(0xffffffffu, mx1, 2));
        float mn0 = fmaxf(m0v, mx0), mn1 = fmaxf(m1v, mx1);
        float a0 = __expf(m0v - mn0), a1 = __expf(m1v - mn1);
        float s0 = 0.f, s1 = 0.f;
        #pragma unroll
        for (int nt = 0; nt < 8; nt++) {
            sacc[nt][0] = __expf(sacc[nt][0] - mn0); s0 += sacc[nt][0];
            sacc[nt][1] = __expf(sacc[nt][1] - mn0); s0 += sacc[nt][1];
            sacc[nt][2] = __expf(sacc[nt][2] - mn1); s1 += sacc[nt][2];
            sacc[nt][3] = __expf(sacc[nt][3] - mn1); s1 += sacc[nt][3];
        }
        s0 += __shfl_xor_sync(0xffffffffu, s0, 1);
        s0 += __shfl_xor_sync(0xffffffffu, s0, 2);
        s1 += __shfl_xor_sync(0xffffffffu, s1, 1);
        s1 += __shfl_xor_sync(0xffffffffu, s1, 2);
        l0 = l0*a0 + s0;  l1 = l1*a1 + s1;
        m0v = mn0;        m1v = mn1;

        // rescale O, stage P (tf32) in smem in warp-private rows
        #pragma unroll
        for (int nt = 0; nt < 8; nt++) {
            o[nt][0] *= a0; o[nt][1] *= a0; o[nt][2] *= a1; o[nt][3] *= a1;
            Ps[(rb+g  )*SPAD + nt*8 + 2*tg    ] = f2tf32(sacc[nt][0]);
            Ps[(rb+g  )*SPAD + nt*8 + 2*tg + 1] = f2tf32(sacc[nt][1]);
            Ps[(rb+g+8)*SPAD + nt*8 + 2*tg    ] = f2tf32(sacc[nt][2]);
            Ps[(rb+g+8)*SPAD + nt*8 + 2*tg + 1] = f2tf32(sacc[nt][3]);
        }
        __syncwarp();

        // O += P @ V : 16 x 64, k-dim = 64
        #pragma unroll
        for (int ks = 0; ks < 8; ks++) {
            const int kc = ks*8;
            float af[4];
            af[0] = Ps[(rb+g  )*SPAD + kc + tg  ];
            af[1] = Ps[(rb+g+8)*SPAD + kc + tg  ];
            af[2] = Ps[(rb+g  )*SPAD + kc + tg+4];
            af[3] = Ps[(rb+g+8)*SPAD + kc + tg+4];
            #pragma unroll
            for (int nt = 0; nt < 8; nt++) {
                float bf[2];
                bf[0] = Vs[(kc+tg  )*SPAD + nt*8 + g];
                bf[1] = Vs[(kc+tg+4)*SPAD + nt*8 + g];
                mma8(o[nt], af, bf);
            }
        }
    }

    // epilogue: O /= l ; write to g_attn [B,S,DMODEL]
    const int b = bh / NHEADS, h = bh % NHEADS;
    const float inv0 = 1.f / l0, inv1 = 1.f / l1;
    #pragma unroll
    for (int nt = 0; nt < 8; nt++) {
        int c = h*HDIM + nt*8 + 2*tg;
        size_t base0 = ((size_t)(b*SEQ + q0 + rb + g    ))*DMODEL + c;
        size_t base1 = ((size_t)(b*SEQ + q0 + rb + g + 8))*DMODEL + c;
        g_attn[base0  ] = o[nt][0]*inv0;
        g_attn[base0+1] = o[nt][1]*inv0;
        g_attn[base1  ] = o[nt][2]*inv1;
        g_attn[base1+1] = o[nt][3]*inv1;
    }
}

// ============================================================================
extern "C" void kernel_launch(void* const* d_in, const int* in_sizes, int n_in,
                              void* d_out, int out_size)
{
    (void)in_sizes; (void)n_in; (void)out_size;
    const float* x    = (const float*)d_in[0];
    const float* wqkv = (const float*)d_in[1];
    const float* wout = (const float*)d_in[2];
    float* out = (float*)d_out;

    void* attn_ptr = nullptr;
    cudaGetSymbolAddress(&attn_ptr, g_attn);

    cudaFuncSetAttribute((const void*)gemm3x<1>,
                         cudaFuncAttributeMaxDynamicSharedMemorySize, GEMM_SMEM_BYTES);
    cudaFuncSetAttribute((const void*)gemm3x<0>,
                         cudaFuncAttributeMaxDynamicSharedMemorySize, GEMM_SMEM_BYTES);
    cudaFuncSetAttribute((const void*)flashattn,
                         cudaFuncAttributeMaxDynamicSharedMemorySize, ATTN_SMEM_BYTES);

    // 1) QKV projection: [8192,1024] @ [1024,3072] -> scatter to g_q/g_k/g_v
    gemm3x<1><<<dim3(3*DMODEL/128, MTOT/128), 256, GEMM_SMEM_BYTES>>>(
        x, wqkv, nullptr, MTOT, 3*DMODEL, DMODEL);

    // 2) flash attention -> g_attn [B,S,D]
    flashattn<<<dim3(SEQ/128, BATCH*NHEADS), 256, ATTN_SMEM_BYTES>>>();

    // 3) out projection: [8192,1024] @ [1024,1024] -> d_out
    gemm3x<0><<<dim3(DMODEL/128, MTOT/128), 256, GEMM_SMEM_BYTES>>>(
        (const float*)attn_ptr, wout, out, MTOT, DMODEL, DMODEL);
}

// round 2
// speedup vs baseline: 1.1756x; 1.1756x over previous
#include <cuda_runtime.h>
#include <stdint.h>

#define BATCH   4
#define SEQ     2048
#define DMODEL  1024
#define NHEADS  16
#define HDIM    64
#define MTOT    (BATCH*SEQ)          // 8192

// ---------------- scratch (static device globals; no runtime allocation) ---
__device__ __align__(16) float g_q[(size_t)BATCH*NHEADS*SEQ*HDIM];
__device__ __align__(16) float g_k[(size_t)BATCH*NHEADS*SEQ*HDIM];
__device__ __align__(16) float g_v[(size_t)BATCH*NHEADS*SEQ*HDIM];
__device__ __align__(16) float g_attn[(size_t)MTOT*DMODEL];

// ---------------- helpers ---------------------------------------------------
__device__ __forceinline__ float f2tf32(float x) {
    uint32_t u;
    asm("cvt.rna.tf32.f32 %0, %1;" : "=r"(u) : "f"(x));
    return __uint_as_float(u);
}

__device__ __forceinline__ void cp16(float* dst_smem, const float* src) {
    uint32_t d = (uint32_t)__cvta_generic_to_shared(dst_smem);
    asm volatile("cp.async.cg.shared.global [%0], [%1], 16;\n" :: "r"(d), "l"(src));
}
__device__ __forceinline__ void cp_commit() {
    asm volatile("cp.async.commit_group;\n");
}
template <int N>
__device__ __forceinline__ void cp_wait() {
    asm volatile("cp.async.wait_group %0;\n" :: "n"(N));
}

// D += A*B, m16n8k8 tf32
__device__ __forceinline__ void mma8(float* c, const float* a, const float* b) {
    const uint32_t* A = reinterpret_cast<const uint32_t*>(a);
    const uint32_t* B = reinterpret_cast<const uint32_t*>(b);
    asm volatile(
        "mma.sync.aligned.m16n8k8.row.col.f32.tf32.tf32.f32 "
        "{%0,%1,%2,%3}, {%4,%5,%6,%7}, {%8,%9}, {%0,%1,%2,%3};\n"
        : "+f"(c[0]), "+f"(c[1]), "+f"(c[2]), "+f"(c[3])
        : "r"(A[0]), "r"(A[1]), "r"(A[2]), "r"(A[3]), "r"(B[0]), "r"(B[1]));
}

// ============================================================================
// GEMM (3xTF32 split at fragment-load time): C[M,N] = A[M,K] @ B[K,N]
// 128x128 tile, BK=32, 256 threads, 2-stage cp.async pipeline, raw fp32 smem.
// EPI=0: row-major store. EPI=1: scatter qkv -> g_q/g_k/g_v.
// ============================================================================
#define APAD 36      // 144B row stride: frag-load bank = lane (conflict-free)
#define BPAD 136     // 544B row stride: 8*tg+g unique (conflict-free)
#define ASTG (128*APAD)            // 4608 floats
#define BSTG (32*BPAD)             // 4352 floats
#define GSTG (ASTG+BSTG)           // floats per stage
#define GEMM_SMEM_BYTES (2*GSTG*4) // 71680

__device__ __forceinline__ void gemm_load_tile(
    float* As, float* Bs, const float* __restrict__ A, const float* __restrict__ Bm,
    int m0, int n0, int k0, int K, int N, int tid)
{
    const int ar = tid >> 3, ac = (tid & 7) * 4;
    #pragma unroll
    for (int j = 0; j < 4; j++) {
        int r = ar + j*32;
        cp16(As + r*APAD + ac, A + (size_t)(m0+r)*K + k0 + ac);
    }
    const int br = tid >> 5, bc = (tid & 31) * 4;
    #pragma unroll
    for (int j = 0; j < 4; j++) {
        int r = br + j*8;
        cp16(Bs + r*BPAD + bc, Bm + (size_t)(k0+r)*N + n0 + bc);
    }
}

template <int EPI>
__global__ void __launch_bounds__(256, 2)
gemm3x(const float* __restrict__ A, const float* __restrict__ Bm,
       float* __restrict__ C, int M, int N, int K)
{
    extern __shared__ float sm[];

    const int tid  = threadIdx.x;
    const int lane = tid & 31, warp = tid >> 5;
    const int wm = warp & 3, wn = warp >> 2;            // 4 x 2 warp grid
    const int g  = lane >> 2, tg = lane & 3;
    const int m0 = blockIdx.y * 128, n0 = blockIdx.x * 128;

    float acc[2][8][4];
    #pragma unroll
    for (int i = 0; i < 2; i++)
        #pragma unroll
        for (int j = 0; j < 8; j++)
            #pragma unroll
            for (int e = 0; e < 4; e++) acc[i][j][e] = 0.f;

    const int nk = K >> 5;
    gemm_load_tile(sm, sm + ASTG, A, Bm, m0, n0, 0, K, N, tid);
    cp_commit();

    for (int kt = 0; kt < nk; kt++) {
        float* As = sm + (kt & 1) * GSTG;
        float* Bs = As + ASTG;
        if (kt + 1 < nk) {
            float* Asn = sm + ((kt+1) & 1) * GSTG;
            gemm_load_tile(Asn, Asn + ASTG, A, Bm, m0, n0, (kt+1)*32, K, N, tid);
            cp_commit();
            cp_wait<1>();
        } else {
            cp_wait<0>();
        }
        __syncthreads();

        #pragma unroll
        for (int ks = 0; ks < 4; ks++) {
            const int kc = ks*8;
            float afH[2][4], afL[2][4];
            #pragma unroll
            for (int mt = 0; mt < 2; mt++) {
                int rb = wm*32 + mt*16;
                float r0 = As[(rb+g  )*APAD + kc + tg  ];
                float r1 = As[(rb+g+8)*APAD + kc + tg  ];
                float r2 = As[(rb+g  )*APAD + kc + tg+4];
                float r3 = As[(rb+g+8)*APAD + kc + tg+4];
                afH[mt][0] = f2tf32(r0); afL[mt][0] = f2tf32(r0 - afH[mt][0]);
                afH[mt][1] = f2tf32(r1); afL[mt][1] = f2tf32(r1 - afH[mt][1]);
                afH[mt][2] = f2tf32(r2); afL[mt][2] = f2tf32(r2 - afH[mt][2]);
                afH[mt][3] = f2tf32(r3); afL[mt][3] = f2tf32(r3 - afH[mt][3]);
            }
            #pragma unroll
            for (int nt = 0; nt < 8; nt++) {
                int cb = wn*64 + nt*8;
                float b0 = Bs[(kc+tg  )*BPAD + cb + g];
                float b1 = Bs[(kc+tg+4)*BPAD + cb + g];
                float bfH[2], bfL[2];
                bfH[0] = f2tf32(b0); bfL[0] = f2tf32(b0 - bfH[0]);
                bfH[1] = f2tf32(b1); bfL[1] = f2tf32(b1 - bfH[1]);
                #pragma unroll
                for (int mt = 0; mt < 2; mt++) {
                    mma8(acc[mt][nt], afH[mt], bfH);   // hi*hi
                    mma8(acc[mt][nt], afL[mt], bfH);   // lo*hi
                    mma8(acc[mt][nt], afH[mt], bfL);   // hi*lo
                }
            }
        }
        __syncthreads();
    }

    // epilogue (float2 stores; columns 2*tg, 2*tg+1 are adjacent)
    #pragma unroll
    for (int mt = 0; mt < 2; mt++) {
        #pragma unroll
        for (int nt = 0; nt < 8; nt++) {
            #pragma unroll
            for (int half = 0; half < 2; half++) {
                int r = m0 + wm*32 + mt*16 + g + (half ? 8 : 0);
                int c = n0 + wn*64 + nt*8 + 2*tg;
                float2 v = make_float2(acc[mt][nt][2*half], acc[mt][nt][2*half+1]);
                if (EPI == 0) {
                    *reinterpret_cast<float2*>(C + (size_t)r*N + c) = v;
                } else {
                    int b = r >> 11, s = r & (SEQ-1);
                    int which = c >> 10, rem = c & (DMODEL-1);
                    int h = rem >> 6, d = rem & (HDIM-1);
                    float* dst = (which == 0) ? g_q : (which == 1) ? g_k : g_v;
                    *reinterpret_cast<float2*>(
                        dst + ((size_t)((b*NHEADS + h)*SEQ + s))*HDIM + d) = v;
                }
            }
        }
    }
}

// ============================================================================
// Flash attention (tf32 mma): grid (S/128, B*H), 256 threads (8 warps).
// 2-stage cp.async pipeline on K/V tiles; tf32 rounding at fragment load.
// Each warp owns 16 q-rows so softmax reductions are 4-lane shuffles.
// ============================================================================
#define SPAD 76      // 304B stride: conflict-free for both K-frag and V-frag
#define QOFF 0                          // 128 x SPAD
#define POFF (128*SPAD)                 // 128 x SPAD
#define KVOFF (2*128*SPAD)              // 2 stages x (K 64xSPAD + V 64xSPAD)
#define KVSTG (2*64*SPAD)
#define ATTN_SMEM_BYTES ((2*128*SPAD + 2*KVSTG)*4)   // 155648

__device__ __forceinline__ void attn_load_kv(
    float* Ks, float* Vs, size_t hbase, int kt, int tid)
{
    const int r0 = tid >> 4, c = (tid & 15) * 4;
    #pragma unroll
    for (int j = 0; j < 4; j++) {
        int r = r0 + j*16;
        size_t off = hbase + (size_t)(kt*64 + r)*HDIM + c;
        cp16(Ks + r*SPAD + c, g_k + off);
        cp16(Vs + r*SPAD + c, g_v + off);
    }
}

__global__ void __launch_bounds__(256)
flashattn()
{
    extern __shared__ float sm[];
    float* Qs = sm + QOFF;
    float* Ps = sm + POFF;

    const int tid  = threadIdx.x;
    const int lane = tid & 31, warp = tid >> 5;
    const int g  = lane >> 2, tg = lane & 3;
    const int bh = blockIdx.y;                 // (b*NHEADS + h)
    const int q0 = blockIdx.x * 128;
    const int rb = warp * 16;                  // warp's q-row base inside tile
    const size_t hbase = (size_t)bh * SEQ * HDIM;
    const float scale = 0.125f;                // 1/sqrt(64)

    // preload kt=0 K/V tiles
    attn_load_kv(sm + KVOFF, sm + KVOFF + 64*SPAD, hbase, 0, tid);
    cp_commit();

    // load Q tile (scaled, tf32-rounded): 128x64 = 2048 float4
    #pragma unroll
    for (int j = 0; j < 8; j++) {
        int i  = tid + j*256;
        int r  = i >> 4, c4 = (i & 15) * 4;
        float4 v = *reinterpret_cast<const float4*>(g_q + hbase + (size_t)(q0+r)*HDIM + c4);
        Qs[r*SPAD+c4+0] = f2tf32(v.x * scale);
        Qs[r*SPAD+c4+1] = f2tf32(v.y * scale);
        Qs[r*SPAD+c4+2] = f2tf32(v.z * scale);
        Qs[r*SPAD+c4+3] = f2tf32(v.w * scale);
    }

    float m0v = -1e30f, m1v = -1e30f;   // running row max (rows g, g+8)
    float l0 = 0.f, l1 = 0.f;           // running row sum
    float o[8][4];
    #pragma unroll
    for (int nt = 0; nt < 8; nt++)
        #pragma unroll
        for (int e = 0; e < 4; e++) o[nt][e] = 0.f;

    const int NKT = SEQ/64;
    for (int kt = 0; kt < NKT; kt++) {
        float* Ks = sm + KVOFF + (kt & 1)*KVSTG;
        float* Vs = Ks + 64*SPAD;
        if (kt + 1 < NKT) {
            float* Ksn = sm + KVOFF + ((kt+1) & 1)*KVSTG;
            attn_load_kv(Ksn, Ksn + 64*SPAD, hbase, kt+1, tid);
            cp_commit();
            cp_wait<1>();
        } else {
            cp_wait<0>();
        }
        __syncthreads();

        // S = Q @ K^T : warp computes 16 x 64
        float sacc[8][4];
        #pragma unroll
        for (int nt = 0; nt < 8; nt++)
            #pragma unroll
            for (int e = 0; e < 4; e++) sacc[nt][e] = 0.f;

        #pragma unroll
        for (int ks = 0; ks < 8; ks++) {
            const int kc = ks*8;
            float af[4];
            af[0] = Qs[(rb+g  )*SPAD + kc + tg  ];
            af[1] = Qs[(rb+g+8)*SPAD + kc + tg  ];
            af[2] = Qs[(rb+g  )*SPAD + kc + tg+4];
            af[3] = Qs[(rb+g+8)*SPAD + kc + tg+4];
            #pragma unroll
            for (int nt = 0; nt < 8; nt++) {
                float bf[2];
                bf[0] = f2tf32(Ks[(nt*8+g)*SPAD + kc + tg  ]);
                bf[1] = f2tf32(Ks[(nt*8+g)*SPAD + kc + tg+4]);
                mma8(sacc[nt], af, bf);
            }
        }

        // online softmax (rows g and g+8 of this warp's 16-row block)
        float mx0 = -1e30f, mx1 = -1e30f;
        #pragma unroll
        for (int nt = 0; nt < 8; nt++) {
            mx0 = fmaxf(mx0, fmaxf(sacc[nt][0], sacc[nt][1]));
            mx1 = fmaxf(mx1, fmaxf(sacc[nt][2], sacc[nt][3]));
        }
        mx0 = fmaxf(mx0, __shfl_xor_sync(0xffffffffu, mx0, 1));
        mx0 = fmaxf(mx0, __shfl_xor_sync(0xffffffffu, mx0, 2));
        mx1 = fmaxf(mx1, __shfl_xor_sync(0xffffffffu, mx1, 1));
        mx1 = fmaxf(mx1, __shfl_xor_sync(0xffffffffu, mx1, 2));
        float mn0 = fmaxf(m0v, mx0), mn1 = fmaxf(m1v, mx1);
        float a0 = __expf(m0v - mn0), a1 = __expf(m1v - mn1);
        float s0 = 0.f, s1 = 0.f;
        #pragma unroll
        for (int nt = 0; nt < 8; nt++) {
            sacc[nt][0] = __expf(sacc[nt][0] - mn0); s0 += sacc[nt][0];
            sacc[nt][1] = __expf(sacc[nt][1] - mn0); s0 += sacc[nt][1];
            sacc[nt][2] = __expf(sacc[nt][2] - mn1); s1 += sacc[nt][2];
            sacc[nt][3] = __expf(sacc[nt][3] - mn1); s1 += sacc[nt][3];
        }
        s0 += __shfl_xor_sync(0xffffffffu, s0, 1);
        s0 += __shfl_xor_sync(0xffffffffu, s0, 2);
        s1 += __shfl_xor_sync(0xffffffffu, s1, 1);
        s1 += __shfl_xor_sync(0xffffffffu, s1, 2);
        l0 = l0*a0 + s0;  l1 = l1*a1 + s1;
        m0v = mn0;        m1v = mn1;

        // rescale O, stage P (tf32) in smem in warp-private rows
        #pragma unroll
        for (int nt = 0; nt < 8; nt++) {
            o[nt][0] *= a0; o[nt][1] *= a0; o[nt][2] *= a1; o[nt][3] *= a1;
            Ps[(rb+g  )*SPAD + nt*8 + 2*tg    ] = f2tf32(sacc[nt][0]);
            Ps[(rb+g  )*SPAD + nt*8 + 2*tg + 1] = f2tf32(sacc[nt][1]);
            Ps[(rb+g+8)*SPAD + nt*8 + 2*tg    ] = f2tf32(sacc[nt][2]);
            Ps[(rb+g+8)*SPAD + nt*8 + 2*tg + 1] = f2tf32(sacc[nt][3]);
        }
        __syncwarp();

        // O += P @ V : 16 x 64, k-dim = 64
        #pragma unroll
        for (int ks = 0; ks < 8; ks++) {
            const int kc = ks*8;
            float af[4];
            af[0] = Ps[(rb+g  )*SPAD + kc + tg  ];
            af[1] = Ps[(rb+g+8)*SPAD + kc + tg  ];
            af[2] = Ps[(rb+g  )*SPAD + kc + tg+4];
            af[3] = Ps[(rb+g+8)*SPAD + kc + tg+4];
            #pragma unroll
            for (int nt = 0; nt < 8; nt++) {
                float bf[2];
                bf[0] = f2tf32(Vs[(kc+tg  )*SPAD + nt*8 + g]);
                bf[1] = f2tf32(Vs[(kc+tg+4)*SPAD + nt*8 + g]);
                mma8(o[nt], af, bf);
            }
        }
        __syncthreads();   // all warps done with Ks/Vs before next cp.async overwrites
    }

    // epilogue: O /= l ; write to g_attn [B,S,DMODEL]
    const int b = bh / NHEADS, h = bh % NHEADS;
    const float inv0 = 1.f / l0, inv1 = 1.f / l1;
    #pragma unroll
    for (int nt = 0; nt < 8; nt++) {
        int c = h*HDIM + nt*8 + 2*tg;
        size_t base0 = ((size_t)(b*SEQ + q0 + rb + g    ))*DMODEL + c;
        size_t base1 = ((size_t)(b*SEQ + q0 + rb + g + 8))*DMODEL + c;
        *reinterpret_cast<float2*>(g_attn + base0) = make_float2(o[nt][0]*inv0, o[nt][1]*inv0);
        *reinterpret_cast<float2*>(g_attn + base1) = make_float2(o[nt][2]*inv1, o[nt][3]*inv1);
    }
}

// ============================================================================
extern "C" void kernel_launch(void* const* d_in, const int* in_sizes, int n_in,
                              void* d_out, int out_size)
{
    (void)in_sizes; (void)n_in; (void)out_size;
    const float* x    = (const float*)d_in[0];
    const float* wqkv = (const float*)d_in[1];
    const float* wout = (const float*)d_in[2];
    float* out = (float*)d_out;

    void* attn_ptr = nullptr;
    cudaGetSymbolAddress(&attn_ptr, g_attn);

    cudaFuncSetAttribute((const void*)gemm3x<1>,
                         cudaFuncAttributeMaxDynamicSharedMemorySize, GEMM_SMEM_BYTES);
    cudaFuncSetAttribute((const void*)gemm3x<0>,
                         cudaFuncAttributeMaxDynamicSharedMemorySize, GEMM_SMEM_BYTES);
    cudaFuncSetAttribute((const void*)flashattn,
                         cudaFuncAttributeMaxDynamicSharedMemorySize, ATTN_SMEM_BYTES);

    // 1) QKV projection: [8192,1024] @ [1024,3072] -> scatter to g_q/g_k/g_v
    gemm3x<1><<<dim3(3*DMODEL/128, MTOT/128), 256, GEMM_SMEM_BYTES>>>(
        x, wqkv, nullptr, MTOT, 3*DMODEL, DMODEL);

    // 2) flash attention -> g_attn [B,S,D]
    flashattn<<<dim3(SEQ/128, BATCH*NHEADS), 256, ATTN_SMEM_BYTES>>>();

    // 3) out projection: [8192,1024] @ [1024,1024] -> d_out
    gemm3x<0><<<dim3(DMODEL/128, MTOT/128), 256, GEMM_SMEM_BYTES>>>(
        (const float*)attn_ptr, wout, out, MTOT, DMODEL, DMODEL);
}

// round 3
// speedup vs baseline: 1.5937x; 1.3556x over previous
#include <cuda_runtime.h>
#include <cuda_bf16.h>
#include <stdint.h>

#define BATCH   4
#define SEQ     2048
#define DMODEL  1024
#define NHEADS  16
#define HDIM    64
#define MTOT    (BATCH*SEQ)          // 8192

typedef __nv_bfloat16 bf16;

// ---------------- scratch (static device globals; no runtime allocation) ---
__device__ __align__(16) float g_q[(size_t)BATCH*NHEADS*SEQ*HDIM];
__device__ __align__(16) float g_k[(size_t)BATCH*NHEADS*SEQ*HDIM];
__device__ __align__(16) float g_v[(size_t)BATCH*NHEADS*SEQ*HDIM];
__device__ __align__(16) float g_attn[(size_t)MTOT*DMODEL];
// bf16 hi/lo planes
__device__ __align__(16) bf16 g_xh[(size_t)MTOT*DMODEL];
__device__ __align__(16) bf16 g_xl[(size_t)MTOT*DMODEL];
__device__ __align__(16) bf16 g_ah[(size_t)MTOT*DMODEL];
__device__ __align__(16) bf16 g_al[(size_t)MTOT*DMODEL];
__device__ __align__(16) bf16 g_wqh[(size_t)3*DMODEL*DMODEL];   // transposed [N][K]
__device__ __align__(16) bf16 g_wql[(size_t)3*DMODEL*DMODEL];
__device__ __align__(16) bf16 g_woh[(size_t)DMODEL*DMODEL];     // transposed [N][K]
__device__ __align__(16) bf16 g_wol[(size_t)DMODEL*DMODEL];

// ---------------- helpers ---------------------------------------------------
__device__ __forceinline__ float f2tf32(float x) {
    uint32_t u;
    asm("cvt.rna.tf32.f32 %0, %1;" : "=r"(u) : "f"(x));
    return __uint_as_float(u);
}
__device__ __forceinline__ void cp16(const void* dst_smem, const void* src) {
    uint32_t d = (uint32_t)__cvta_generic_to_shared(dst_smem);
    asm volatile("cp.async.cg.shared.global [%0], [%1], 16;\n" :: "r"(d), "l"(src));
}
__device__ __forceinline__ void cp_commit() {
    asm volatile("cp.async.commit_group;\n");
}
template <int N>
__device__ __forceinline__ void cp_wait() {
    asm volatile("cp.async.wait_group %0;\n" :: "n"(N));
}

// D += A*B, m16n8k8 tf32 (attention)
__device__ __forceinline__ void mma8(float* c, const float* a, const float* b) {
    const uint32_t* A = reinterpret_cast<const uint32_t*>(a);
    const uint32_t* B = reinterpret_cast<const uint32_t*>(b);
    asm volatile(
        "mma.sync.aligned.m16n8k8.row.col.f32.tf32.tf32.f32 "
        "{%0,%1,%2,%3}, {%4,%5,%6,%7}, {%8,%9}, {%0,%1,%2,%3};\n"
        : "+f"(c[0]), "+f"(c[1]), "+f"(c[2]), "+f"(c[3])
        : "r"(A[0]), "r"(A[1]), "r"(A[2]), "r"(A[3]), "r"(B[0]), "r"(B[1]));
}
// D += A*B, m16n8k16 bf16 (GEMMs)
__device__ __forceinline__ void mma16(float* c, const uint32_t* a, const uint32_t* b) {
    asm volatile(
        "mma.sync.aligned.m16n8k16.row.col.f32.bf16.bf16.f32 "
        "{%0,%1,%2,%3}, {%4,%5,%6,%7}, {%8,%9}, {%0,%1,%2,%3};\n"
        : "+f"(c[0]), "+f"(c[1]), "+f"(c[2]), "+f"(c[3])
        : "r"(a[0]), "r"(a[1]), "r"(a[2]), "r"(a[3]), "r"(b[0]), "r"(b[1]));
}

__device__ __forceinline__ void split1(float v, bf16& h, bf16& l) {
    h = __float2bfloat16_rn(v);
    l = __float2bfloat16_rn(v - __bfloat162float(h));
}

// ============================================================================
// prep: plain hi/lo split (same layout)
// ============================================================================
__global__ void __launch_bounds__(256)
split_plain(const float* __restrict__ src, bf16* __restrict__ hi,
            bf16* __restrict__ lo, int n4)
{
    int i = blockIdx.x * blockDim.x + threadIdx.x;
    if (i >= n4) return;
    float4 v = reinterpret_cast<const float4*>(src)[i];
    bf16 h0,l0,h1,l1,h2,l2,h3,l3;
    split1(v.x,h0,l0); split1(v.y,h1,l1); split1(v.z,h2,l2); split1(v.w,h3,l3);
    ushort4 H = make_ushort4(__bfloat16_as_ushort(h0),__bfloat16_as_ushort(h1),
                             __bfloat16_as_ushort(h2),__bfloat16_as_ushort(h3));
    ushort4 L = make_ushort4(__bfloat16_as_ushort(l0),__bfloat16_as_ushort(l1),
                             __bfloat16_as_ushort(l2),__bfloat16_as_ushort(l3));
    reinterpret_cast<ushort4*>(hi)[i] = H;
    reinterpret_cast<ushort4*>(lo)[i] = L;
}

// ============================================================================
// prep: transpose + hi/lo split. src[K][N] fp32 -> hiT/loT [N][K] bf16
// ============================================================================
__global__ void __launch_bounds__(256)
split_T(const float* __restrict__ src, bf16* __restrict__ hiT,
        bf16* __restrict__ loT, int K, int N)
{
    __shared__ float t[32][33];
    int n0 = blockIdx.x * 32, k0 = blockIdx.y * 32;
    int tx = threadIdx.x & 31, ty = threadIdx.x >> 5;   // 32 x 8
    #pragma unroll
    for (int j = 0; j < 4; j++)
        t[ty + 8*j][tx] = src[(size_t)(k0 + ty + 8*j)*N + n0 + tx];
    __syncthreads();
    #pragma unroll
    for (int j = 0; j < 4; j++) {
        float v = t[tx][ty + 8*j];
        bf16 h, l; split1(v, h, l);
        size_t o = (size_t)(n0 + ty + 8*j)*K + k0 + tx;
        hiT[o] = h; loT[o] = l;
    }
}

// ============================================================================
// GEMM (bf16x3): C[M,N] = A[M,K] @ B[K,N], A planes [M][K], B planes [N][K] (T)
// 128x128 tile, BK=32, 256 threads, 2-stage cp.async, all-bf16 smem.
// EPI=0: row-major store. EPI=1: scatter qkv -> g_q/g_k/g_v.
// ============================================================================
#define ARS 40                         // bf16 per smem row (32 data + 8 pad = 80B)
#define AH_OFF 0
#define AL_OFF (128*ARS)
#define BH_OFF (2*128*ARS)
#define BL_OFF (3*128*ARS)
#define STG_BF (4*128*ARS)             // 20480 bf16 = 40KB per stage
#define GEMM_SMEM_BYTES (2*STG_BF*2)   // 81920

__device__ __forceinline__ void gemm_load_tile(
    bf16* st, const bf16* __restrict__ Ah, const bf16* __restrict__ Al,
    const bf16* __restrict__ BTh, const bf16* __restrict__ BTl,
    int m0, int n0, int k0, int K, int tid)
{
    #pragma unroll
    for (int i = 0; i < 2; i++) {
        int id = tid + i*256;
        int r = id >> 2, c = (id & 3) * 8;
        cp16(st + AH_OFF + r*ARS + c, Ah  + (size_t)(m0+r)*K + k0 + c);
        cp16(st + AL_OFF + r*ARS + c, Al  + (size_t)(m0+r)*K + k0 + c);
        cp16(st + BH_OFF + r*ARS + c, BTh + (size_t)(n0+r)*K + k0 + c);
        cp16(st + BL_OFF + r*ARS + c, BTl + (size_t)(n0+r)*K + k0 + c);
    }
}

template <int EPI>
__global__ void __launch_bounds__(256, 2)
gemm_bf3(const bf16* __restrict__ Ah, const bf16* __restrict__ Al,
         const bf16* __restrict__ BTh, const bf16* __restrict__ BTl,
         float* __restrict__ C, int M, int N, int K)
{
    extern __shared__ __align__(16) char smraw[];
    bf16* smb = reinterpret_cast<bf16*>(smraw);

    const int tid  = threadIdx.x;
    const int lane = tid & 31, warp = tid >> 5;
    const int wm = warp & 3, wn = warp >> 2;            // 4 x 2 warp grid
    const int g  = lane >> 2, tg = lane & 3;
    const int m0 = blockIdx.y * 128, n0 = blockIdx.x * 128;

    float acc[2][8][4];
    #pragma unroll
    for (int i = 0; i < 2; i++)
        #pragma unroll
        for (int j = 0; j < 8; j++)
            #pragma unroll
            for (int e = 0; e < 4; e++) acc[i][j][e] = 0.f;

    const int nk = K >> 5;
    gemm_load_tile(smb, Ah, Al, BTh, BTl, m0, n0, 0, K, tid);
    cp_commit();

    for (int kt = 0; kt < nk; kt++) {
        bf16* st = smb + (kt & 1) * STG_BF;
        if (kt + 1 < nk) {
            gemm_load_tile(smb + ((kt+1) & 1)*STG_BF, Ah, Al, BTh, BTl,
                           m0, n0, (kt+1)*32, K, tid);
            cp_commit();
            cp_wait<1>();
        } else {
            cp_wait<0>();
        }
        __syncthreads();

        #pragma unroll
        for (int s = 0; s < 2; s++) {
            const int ko = s*16;
            uint32_t ah[2][4], al[2][4];
            #pragma unroll
            for (int mt = 0; mt < 2; mt++) {
                int rb = wm*32 + mt*16;
                ah[mt][0] = *reinterpret_cast<uint32_t*>(st + AH_OFF + (rb+g  )*ARS + ko + 2*tg);
                ah[mt][1] = *reinterpret_cast<uint32_t*>(st + AH_OFF + (rb+g+8)*ARS + ko + 2*tg);
                ah[mt][2] = *reinterpret_cast<uint32_t*>(st + AH_OFF + (rb+g  )*ARS + ko + 8 + 2*tg);
                ah[mt][3] = *reinterpret_cast<uint32_t*>(st + AH_OFF + (rb+g+8)*ARS + ko + 8 + 2*tg);
                al[mt][0] = *reinterpret_cast<uint32_t*>(st + AL_OFF + (rb+g  )*ARS + ko + 2*tg);
                al[mt][1] = *reinterpret_cast<uint32_t*>(st + AL_OFF + (rb+g+8)*ARS + ko + 2*tg);
                al[mt][2] = *reinterpret_cast<uint32_t*>(st + AL_OFF + (rb+g  )*ARS + ko + 8 + 2*tg);
                al[mt][3] = *reinterpret_cast<uint32_t*>(st + AL_OFF + (rb+g+8)*ARS + ko + 8 + 2*tg);
            }
            #pragma unroll
            for (int nt = 0; nt < 8; nt++) {
                int cb = wn*64 + nt*8;
                uint32_t bh[2], bl[2];
                bh[0] = *reinterpret_cast<uint32_t*>(st + BH_OFF + (cb+g)*ARS + ko + 2*tg);
                bh[1] = *reinterpret_cast<uint32_t*>(st + BH_OFF + (cb+g)*ARS + ko + 8 + 2*tg);
                bl[0] = *reinterpret_cast<uint32_t*>(st + BL_OFF + (cb+g)*ARS + ko + 2*tg);
                bl[1] = *reinterpret_cast<uint32_t*>(st + BL_OFF + (cb+g)*ARS + ko + 8 + 2*tg);
                #pragma unroll
                for (int mt = 0; mt < 2; mt++) {
                    mma16(acc[mt][nt], ah[mt], bh);   // hi*hi
                    mma16(acc[mt][nt], al[mt], bh);   // lo*hi
                    mma16(acc[mt][nt], ah[mt], bl);   // hi*lo
                }
            }
        }
        __syncthreads();
    }

    // epilogue (float2 stores; columns 2*tg, 2*tg+1 adjacent)
    #pragma unroll
    for (int mt = 0; mt < 2; mt++) {
        #pragma unroll
        for (int nt = 0; nt < 8; nt++) {
            #pragma unroll
            for (int half = 0; half < 2; half++) {
                int r = m0 + wm*32 + mt*16 + g + (half ? 8 : 0);
                int c = n0 + wn*64 + nt*8 + 2*tg;
                float2 v = make_float2(acc[mt][nt][2*half], acc[mt][nt][2*half+1]);
                if (EPI == 0) {
                    *reinterpret_cast<float2*>(C + (size_t)r*N + c) = v;
                } else {
                    int b = r >> 11, s = r & (SEQ-1);
                    int which = c >> 10, rem = c & (DMODEL-1);
                    int h = rem >> 6, d = rem & (HDIM-1);
                    float* dst = (which == 0) ? g_q : (which == 1) ? g_k : g_v;
                    *reinterpret_cast<float2*>(
                        dst + ((size_t)((b*NHEADS + h)*SEQ + s))*HDIM + d) = v;
                }
            }
        }
    }
}

// ============================================================================
// Flash attention (tf32 mma): grid (S/128, B*H), 256 threads (8 warps).
// 3-stage cp.async KV ring (single __syncthreads per iteration).
// ============================================================================
#define SPAD 76
#define QOFF 0                          // 128 x SPAD
#define POFF (128*SPAD)                 // 128 x SPAD
#define KVOFF (2*128*SPAD)              // 3 stages x (K 64xSPAD + V 64xSPAD)
#define KVSTG (2*64*SPAD)
#define ATTN_SMEM_BYTES ((2*128*SPAD + 3*KVSTG)*4)   // 194560

__device__ __forceinline__ void attn_load_kv(
    float* Ks, float* Vs, size_t hbase, int kt, int tid)
{
    const int r0 = tid >> 4, c = (tid & 15) * 4;
    #pragma unroll
    for (int j = 0; j < 4; j++) {
        int r = r0 + j*16;
        size_t off = hbase + (size_t)(kt*64 + r)*HDIM + c;
        cp16(Ks + r*SPAD + c, g_k + off);
        cp16(Vs + r*SPAD + c, g_v + off);
    }
}

__global__ void __launch_bounds__(256)
flashattn()
{
    extern __shared__ float sm[];
    float* Qs = sm + QOFF;
    float* Ps = sm + POFF;

    const int tid  = threadIdx.x;
    const int lane = tid & 31, warp = tid >> 5;
    const int g  = lane >> 2, tg = lane & 3;
    const int bh = blockIdx.y;                 // (b*NHEADS + h)
    const int q0 = blockIdx.x * 128;
    const int rb = warp * 16;                  // warp's q-row base inside tile
    const size_t hbase = (size_t)bh * SEQ * HDIM;
    const float scale = 0.125f;                // 1/sqrt(64)

    // preload kt=0,1 K/V tiles
    attn_load_kv(sm + KVOFF, sm + KVOFF + 64*SPAD, hbase, 0, tid);
    cp_commit();
    attn_load_kv(sm + KVOFF + KVSTG, sm + KVOFF + KVSTG + 64*SPAD, hbase, 1, tid);
    cp_commit();

    // load Q tile (scaled, tf32-rounded): 128x64
    #pragma unroll
    for (int j = 0; j < 8; j++) {
        int i  = tid + j*256;
        int r  = i >> 4, c4 = (i & 15) * 4;
        float4 v = *reinterpret_cast<const float4*>(g_q + hbase + (size_t)(q0+r)*HDIM + c4);
        Qs[r*SPAD+c4+0] = f2tf32(v.x * scale);
        Qs[r*SPAD+c4+1] = f2tf32(v.y * scale);
        Qs[r*SPAD+c4+2] = f2tf32(v.z * scale);
        Qs[r*SPAD+c4+3] = f2tf32(v.w * scale);
    }

    float m0v = -1e30f, m1v = -1e30f;
    float l0 = 0.f, l1 = 0.f;
    float o[8][4];
    #pragma unroll
    for (int nt = 0; nt < 8; nt++)
        #pragma unroll
        for (int e = 0; e < 4; e++) o[nt][e] = 0.f;

    const int NKT = SEQ/64;
    for (int kt = 0; kt < NKT; kt++) {
        float* Ks = sm + KVOFF + (kt % 3)*KVSTG;
        float* Vs = Ks + 64*SPAD;
        if (kt + 2 < NKT) {
            float* Ksn = sm + KVOFF + ((kt+2) % 3)*KVSTG;
            attn_load_kv(Ksn, Ksn + 64*SPAD, hbase, kt+2, tid);
            cp_commit();
            cp_wait<2>();
        } else if (kt + 1 < NKT) {
            cp_wait<1>();
        } else {
            cp_wait<0>();
        }
        __syncthreads();

        // S = Q @ K^T : warp computes 16 x 64
        float sacc[8][4];
        #pragma unroll
        for (int nt = 0; nt < 8; nt++)
            #pragma unroll
            for (int e = 0; e < 4; e++) sacc[nt][e] = 0.f;

        #pragma unroll
        for (int ks = 0; ks < 8; ks++) {
            const int kc = ks*8;
            float af[4];
            af[0] = Qs[(rb+g  )*SPAD + kc + tg  ];
            af[1] = Qs[(rb+g+8)*SPAD + kc + tg  ];
            af[2] = Qs[(rb+g  )*SPAD + kc + tg+4];
            af[3] = Qs[(rb+g+8)*SPAD + kc + tg+4];
            #pragma unroll
            for (int nt = 0; nt < 8; nt++) {
                float bf[2];
                bf[0] = f2tf32(Ks[(nt*8+g)*SPAD + kc + tg  ]);
                bf[1] = f2tf32(Ks[(nt*8+g)*SPAD + kc + tg+4]);
                mma8(sacc[nt], af, bf);
            }
        }

        // online softmax
        float mx0 = -1e30f, mx1 = -1e30f;
        #pragma unroll
        for (int nt = 0; nt < 8; nt++) {
            mx0 = fmaxf(mx0, fmaxf(sacc[nt][0], sacc[nt][1]));
            mx1 = fmaxf(mx1, fmaxf(sacc[nt][2], sacc[nt][3]));
        }
        mx0 = fmaxf(mx0, __shfl_xor_sync(0xffffffffu, mx0, 1));
        mx0 = fmaxf(mx0, __shfl_xor_sync(0xffffffffu, mx0, 2));
        mx1 = fmaxf(mx1, __shfl_xor_sync(0xffffffffu, mx1, 1));
        mx1 = fmaxf(mx1, __shfl_xor_sync(0xffffffffu, mx1, 2));
        float mn0 = fmaxf(m0v, mx0), mn1 = fmaxf(m1v, mx1);
        float a0 = __expf(m0v - mn0), a1 = __expf(m1v - mn1);
        float s0 = 0.f, s1 = 0.f;
        #pragma unroll
        for (int nt = 0; nt < 8; nt++) {
            sacc[nt][0] = __expf(sacc[nt][0] - mn0); s0 += sacc[nt][0];
            sacc[nt][1] = __expf(sacc[nt][1] - mn0); s0 += sacc[nt][1];
            sacc[nt][2] = __expf(sacc[nt][2] - mn1); s1 += sacc[nt][2];
            sacc[nt][3] = __expf(sacc[nt][3] - mn1); s1 += sacc[nt][3];
        }
        s0 += __shfl_xor_sync(0xffffffffu, s0, 1);
        s0 += __shfl_xor_sync(0xffffffffu, s0, 2);
        s1 += __shfl_xor_sync(0xffffffffu, s1, 1);
        s1 += __shfl_xor_sync(0xffffffffu, s1, 2);
        l0 = l0*a0 + s0;  l1 = l1*a1 + s1;
        m0v = mn0;        m1v = mn1;

        // rescale O, stage P (tf32) in warp-private smem rows
        #pragma unroll
        for (int nt = 0; nt < 8; nt++) {
            o[nt][0] *= a0; o[nt][1] *= a0; o[nt][2] *= a1; o[nt][3] *= a1;
            Ps[(rb+g  )*SPAD + nt*8 + 2*tg    ] = f2tf32(sacc[nt][0]);
            Ps[(rb+g  )*SPAD + nt*8 + 2*tg + 1] = f2tf32(sacc[nt][1]);
            Ps[(rb+g+8)*SPAD + nt*8 + 2*tg    ] = f2tf32(sacc[nt][2]);
            Ps[(rb+g+8)*SPAD + nt*8 + 2*tg + 1] = f2tf32(sacc[nt][3]);
        }
        __syncwarp();

        // O += P @ V
        #pragma unroll
        for (int ks = 0; ks < 8; ks++) {
            const int kc = ks*8;
            float af[4];
            af[0] = Ps[(rb+g  )*SPAD + kc + tg  ];
            af[1] = Ps[(rb+g+8)*SPAD + kc + tg  ];
            af[2] = Ps[(rb+g  )*SPAD + kc + tg+4];
            af[3] = Ps[(rb+g+8)*SPAD + kc + tg+4];
            #pragma unroll
            for (int nt = 0; nt < 8; nt++) {
                float bf[2];
                bf[0] = f2tf32(Vs[(kc+tg  )*SPAD + nt*8 + g]);
                bf[1] = f2tf32(Vs[(kc+tg+4)*SPAD + nt*8 + g]);
                mma8(o[nt], af, bf);
            }
        }
        // no tail sync: 3-stage ring + top-of-loop barrier protects reuse
    }

    // epilogue: O /= l ; write to g_attn [B,S,DMODEL]
    const int b = bh / NHEADS, h = bh % NHEADS;
    const float inv0 = 1.f / l0, inv1 = 1.f / l1;
    #pragma unroll
    for (int nt = 0; nt < 8; nt++) {
        int c = h*HDIM + nt*8 + 2*tg;
        size_t base0 = ((size_t)(b*SEQ + q0 + rb + g    ))*DMODEL + c;
        size_t base1 = ((size_t)(b*SEQ + q0 + rb + g + 8))*DMODEL + c;
        *reinterpret_cast<float2*>(g_attn + base0) = make_float2(o[nt][0]*inv0, o[nt][1]*inv0);
        *reinterpret_cast<float2*>(g_attn + base1) = make_float2(o[nt][2]*inv1, o[nt][3]*inv1);
    }
}

// ============================================================================
extern "C" void kernel_launch(void* const* d_in, const int* in_sizes, int n_in,
                              void* d_out, int out_size)
{
    (void)in_sizes; (void)n_in; (void)out_size;
    const float* x    = (const float*)d_in[0];
    const float* wqkv = (const float*)d_in[1];
    const float* wout = (const float*)d_in[2];
    float* out = (float*)d_out;

    void *xh, *xl, *ah, *al, *wqh, *wql, *woh, *wol, *attn;
    cudaGetSymbolAddress(&xh, g_xh);   cudaGetSymbolAddress(&xl, g_xl);
    cudaGetSymbolAddress(&ah, g_ah);   cudaGetSymbolAddress(&al, g_al);
    cudaGetSymbolAddress(&wqh, g_wqh); cudaGetSymbolAddress(&wql, g_wql);
    cudaGetSymbolAddress(&woh, g_woh); cudaGetSymbolAddress(&wol, g_wol);
    cudaGetSymbolAddress(&attn, g_attn);

    cudaFuncSetAttribute((const void*)gemm_bf3<1>,
                         cudaFuncAttributeMaxDynamicSharedMemorySize, GEMM_SMEM_BYTES);
    cudaFuncSetAttribute((const void*)gemm_bf3<0>,
                         cudaFuncAttributeMaxDynamicSharedMemorySize, GEMM_SMEM_BYTES);
    cudaFuncSetAttribute((const void*)flashattn,
                         cudaFuncAttributeMaxDynamicSharedMemorySize, ATTN_SMEM_BYTES);

    // prep: split x; split+transpose weights
    split_plain<<<(MTOT*DMODEL/4 + 255)/256, 256>>>(x, (bf16*)xh, (bf16*)xl, MTOT*DMODEL/4);
    split_T<<<dim3(3*DMODEL/32, DMODEL/32), 256>>>(wqkv, (bf16*)wqh, (bf16*)wql, DMODEL, 3*DMODEL);
    split_T<<<dim3(DMODEL/32, DMODEL/32), 256>>>(wout, (bf16*)woh, (bf16*)wol, DMODEL, DMODEL);

    // 1) QKV projection: [8192,1024] @ [1024,3072] -> scatter to g_q/g_k/g_v
    gemm_bf3<1><<<dim3(3*DMODEL/128, MTOT/128), 256, GEMM_SMEM_BYTES>>>(
        (const bf16*)xh, (const bf16*)xl, (const bf16*)wqh, (const bf16*)wql,
        nullptr, MTOT, 3*DMODEL, DMODEL);

    // 2) flash attention -> g_attn [B,S,D]
    flashattn<<<dim3(SEQ/128, BATCH*NHEADS), 256, ATTN_SMEM_BYTES>>>();

    // prep: split attention output
    split_plain<<<(MTOT*DMODEL/4 + 255)/256, 256>>>((const float*)attn, (bf16*)ah, (bf16*)al,
                                                    MTOT*DMODEL/4);

    // 3) out projection: [8192,1024] @ [1024,1024] -> d_out
    gemm_bf3<0><<<dim3(DMODEL/128, MTOT/128), 256, GEMM_SMEM_BYTES>>>(
        (const bf16*)ah, (const bf16*)al, (const bf16*)woh, (const bf16*)wol,
        out, MTOT, DMODEL, DMODEL);
}

// round 6
// speedup vs baseline: 1.8363x; 1.1522x over previous
#include <cuda_runtime.h>
#include <cuda_bf16.h>
#include <stdint.h>

#define BATCH   4
#define SEQ     2048
#define DMODEL  1024
#define NHEADS  16
#define HDIM    64
#define MTOT    (BATCH*SEQ)          // 8192

typedef __nv_bfloat16 bf16;

// ---------------- scratch (static device globals; no runtime allocation) ---
__device__ __align__(16) float g_q[(size_t)BATCH*NHEADS*SEQ*HDIM];
__device__ __align__(16) float g_k[(size_t)BATCH*NHEADS*SEQ*HDIM];
__device__ __align__(16) float g_v[(size_t)BATCH*NHEADS*SEQ*HDIM];
__device__ __align__(16) float g_attn[(size_t)MTOT*DMODEL];
// bf16 hi/lo planes
__device__ __align__(16) bf16 g_xh[(size_t)MTOT*DMODEL];
__device__ __align__(16) bf16 g_xl[(size_t)MTOT*DMODEL];
__device__ __align__(16) bf16 g_ah[(size_t)MTOT*DMODEL];
__device__ __align__(16) bf16 g_al[(size_t)MTOT*DMODEL];
__device__ __align__(16) bf16 g_wqh[(size_t)3*DMODEL*DMODEL];   // transposed [N][K]
__device__ __align__(16) bf16 g_wql[(size_t)3*DMODEL*DMODEL];
__device__ __align__(16) bf16 g_woh[(size_t)DMODEL*DMODEL];     // transposed [N][K]
__device__ __align__(16) bf16 g_wol[(size_t)DMODEL*DMODEL];

// ---------------- helpers ---------------------------------------------------
__device__ __forceinline__ float f2tf32(float x) {
    uint32_t u;
    asm("cvt.rna.tf32.f32 %0, %1;" : "=r"(u) : "f"(x));
    return __uint_as_float(u);
}
__device__ __forceinline__ void cp16(const void* dst_smem, const void* src) {
    uint32_t d = (uint32_t)__cvta_generic_to_shared(dst_smem);
    asm volatile("cp.async.cg.shared.global [%0], [%1], 16;\n" :: "r"(d), "l"(src));
}
__device__ __forceinline__ void cp_commit() {
    asm volatile("cp.async.commit_group;\n");
}
template <int N>
__device__ __forceinline__ void cp_wait() {
    asm volatile("cp.async.wait_group %0;\n" :: "n"(N));
}
__device__ __forceinline__ void ldsm4(uint32_t& r0, uint32_t& r1, uint32_t& r2,
                                      uint32_t& r3, uint32_t addr) {
    asm volatile("ldmatrix.sync.aligned.m8n8.x4.shared.b16 {%0,%1,%2,%3}, [%4];\n"
                 : "=r"(r0), "=r"(r1), "=r"(r2), "=r"(r3) : "r"(addr));
}

// D += A*B, m16n8k8 tf32 (attention)
__device__ __forceinline__ void mma8(float* c, const float* a, const float* b) {
    const uint32_t* A = reinterpret_cast<const uint32_t*>(a);
    const uint32_t* B = reinterpret_cast<const uint32_t*>(b);
    asm volatile(
        "mma.sync.aligned.m16n8k8.row.col.f32.tf32.tf32.f32 "
        "{%0,%1,%2,%3}, {%4,%5,%6,%7}, {%8,%9}, {%0,%1,%2,%3};\n"
        : "+f"(c[0]), "+f"(c[1]), "+f"(c[2]), "+f"(c[3])
        : "r"(A[0]), "r"(A[1]), "r"(A[2]), "r"(A[3]), "r"(B[0]), "r"(B[1]));
}
// D += A*B, m16n8k16 bf16 (GEMMs)
__device__ __forceinline__ void mma16(float* c, const uint32_t* a,
                                      uint32_t b0, uint32_t b1) {
    asm volatile(
        "mma.sync.aligned.m16n8k16.row.col.f32.bf16.bf16.f32 "
        "{%0,%1,%2,%3}, {%4,%5,%6,%7}, {%8,%9}, {%0,%1,%2,%3};\n"
        : "+f"(c[0]), "+f"(c[1]), "+f"(c[2]), "+f"(c[3])
        : "r"(a[0]), "r"(a[1]), "r"(a[2]), "r"(a[3]), "r"(b0), "r"(b1));
}

__device__ __forceinline__ void split1(float v, bf16& h, bf16& l) {
    h = __float2bfloat16_rn(v);
    l = __float2bfloat16_rn(v - __bfloat162float(h));
}

// ============================================================================
// prep kernels
// ============================================================================
__global__ void __launch_bounds__(256)
split_plain(const float* __restrict__ src, bf16* __restrict__ hi,
            bf16* __restrict__ lo, int n4)
{
    int i = blockIdx.x * blockDim.x + threadIdx.x;
    if (i >= n4) return;
    float4 v = reinterpret_cast<const float4*>(src)[i];
    bf16 h0,l0,h1,l1,h2,l2,h3,l3;
    split1(v.x,h0,l0); split1(v.y,h1,l1); split1(v.z,h2,l2); split1(v.w,h3,l3);
    ushort4 H = make_ushort4(__bfloat16_as_ushort(h0),__bfloat16_as_ushort(h1),
                             __bfloat16_as_ushort(h2),__bfloat16_as_ushort(h3));
    ushort4 L = make_ushort4(__bfloat16_as_ushort(l0),__bfloat16_as_ushort(l1),
                             __bfloat16_as_ushort(l2),__bfloat16_as_ushort(l3));
    reinterpret_cast<ushort4*>(hi)[i] = H;
    reinterpret_cast<ushort4*>(lo)[i] = L;
}

__global__ void __launch_bounds__(256)
split_T(const float* __restrict__ src, bf16* __restrict__ hiT,
        bf16* __restrict__ loT, int K, int N)
{
    __shared__ float t[32][33];
    int n0 = blockIdx.x * 32, k0 = blockIdx.y * 32;
    int tx = threadIdx.x & 31, ty = threadIdx.x >> 5;   // 32 x 8
    #pragma unroll
    for (int j = 0; j < 4; j++)
        t[ty + 8*j][tx] = src[(size_t)(k0 + ty + 8*j)*N + n0 + tx];
    __syncthreads();
    #pragma unroll
    for (int j = 0; j < 4; j++) {
        float v = t[tx][ty + 8*j];
        bf16 h, l; split1(v, h, l);
        size_t o = (size_t)(n0 + ty + 8*j)*K + k0 + tx;
        hiT[o] = h; loT[o] = l;
    }
}

// ============================================================================
// GEMM (bf16x3, ldmatrix frags): C[M,N] = A[M,K] @ B[K,N]
// A planes [M][K], B planes [N][K] (transposed). 128x128 tile, BK=32,
// 256 threads, 2-stage cp.async, single barrier per k-tile.
// ============================================================================
#define ARS 40                         // bf16 per smem row (32 data + 8 pad)
#define AH_OFF 0
#define AL_OFF (128*ARS)
#define BH_OFF (2*128*ARS)
#define BL_OFF (3*128*ARS)
#define STG_BF (4*128*ARS)             // 20480 bf16 = 40KB per stage
#define GEMM_SMEM_BYTES (2*STG_BF*2)   // 81920

__device__ __forceinline__ void gemm_load_tile(
    bf16* st, const bf16* __restrict__ Ah, const bf16* __restrict__ Al,
    const bf16* __restrict__ BTh, const bf16* __restrict__ BTl,
    int m0, int n0, int k0, int K, int tid)
{
    #pragma unroll
    for (int i = 0; i < 2; i++) {
        int id = tid + i*256;
        int r = id >> 2, c = (id & 3) * 8;
        cp16(st + AH_OFF + r*ARS + c, Ah  + (size_t)(m0+r)*K + k0 + c);
        cp16(st + AL_OFF + r*ARS + c, Al  + (size_t)(m0+r)*K + k0 + c);
        cp16(st + BH_OFF + r*ARS + c, BTh + (size_t)(n0+r)*K + k0 + c);
        cp16(st + BL_OFF + r*ARS + c, BTl + (size_t)(n0+r)*K + k0 + c);
    }
}

template <int EPI>
__global__ void __launch_bounds__(256, 2)
gemm_bf3(const bf16* __restrict__ Ah, const bf16* __restrict__ Al,
         const bf16* __restrict__ BTh, const bf16* __restrict__ BTl,
         float* __restrict__ C, int M, int N, int K)
{
    extern __shared__ __align__(16) char smraw[];
    bf16* smb = reinterpret_cast<bf16*>(smraw);
    const uint32_t sbase = (uint32_t)__cvta_generic_to_shared(smb);

    const int tid  = threadIdx.x;
    const int lane = tid & 31, warp = tid >> 5;
    const int wm = warp & 3, wn = warp >> 2;            // 4 x 2 warp grid
    const int g  = lane >> 2, tg = lane & 3;
    const int m0 = blockIdx.y * 128, n0 = blockIdx.x * 128;

    // ldmatrix per-lane address components
    const int lrow = lane & 15;              // row within 16-row block
    const int lcol = (lane >> 4) << 3;       // 0 or 8 (bf16 col offset)

    float acc[2][8][4];
    #pragma unroll
    for (int i = 0; i < 2; i++)
        #pragma unroll
        for (int j = 0; j < 8; j++)
            #pragma unroll
            for (int e = 0; e < 4; e++) acc[i][j][e] = 0.f;

    const int nk = K >> 5;
    gemm_load_tile(smb, Ah, Al, BTh, BTl, m0, n0, 0, K, tid);
    cp_commit();

    for (int kt = 0; kt < nk; kt++) {
        const uint32_t stoff = (kt & 1) * STG_BF;
        cp_wait<0>();
        __syncthreads();
        if (kt + 1 < nk) {
            gemm_load_tile(smb + ((kt+1) & 1)*STG_BF, Ah, Al, BTh, BTl,
                           m0, n0, (kt+1)*32, K, tid);
            cp_commit();
        }

        #pragma unroll
        for (int s = 0; s < 2; s++) {
            const int ko = s*16;
            uint32_t ah[2][4], al[2][4];
            #pragma unroll
            for (int mt = 0; mt < 2; mt++) {
                int rb = wm*32 + mt*16 + lrow;
                uint32_t base = sbase + ((stoff + rb*ARS + ko + lcol) << 1);
                ldsm4(ah[mt][0], ah[mt][1], ah[mt][2], ah[mt][3], base + (AH_OFF<<1));
                ldsm4(al[mt][0], al[mt][1], al[mt][2], al[mt][3], base + (AL_OFF<<1));
            }
            #pragma unroll
            for (int ntp = 0; ntp < 4; ntp++) {
                int cb = wn*64 + ntp*16 + lrow;
                uint32_t base = sbase + ((stoff + cb*ARS + ko + lcol) << 1);
                uint32_t bh0, bh1, bh2, bh3, bl0, bl1, bl2, bl3;
                ldsm4(bh0, bh1, bh2, bh3, base + (BH_OFF<<1));
                ldsm4(bl0, bl1, bl2, bl3, base + (BL_OFF<<1));
                #pragma unroll
                for (int mt = 0; mt < 2; mt++) {
                    mma16(acc[mt][2*ntp  ], ah[mt], bh0, bh2);   // hi*hi
                    mma16(acc[mt][2*ntp  ], al[mt], bh0, bh2);   // lo*hi
                    mma16(acc[mt][2*ntp  ], ah[mt], bl0, bl2);   // hi*lo
                    mma16(acc[mt][2*ntp+1], ah[mt], bh1, bh3);
                    mma16(acc[mt][2*ntp+1], al[mt], bh1, bh3);
                    mma16(acc[mt][2*ntp+1], ah[mt], bl1, bl3);
                }
            }
        }
    }

    // epilogue (float2 stores)
    #pragma unroll
    for (int mt = 0; mt < 2; mt++) {
        #pragma unroll
        for (int nt = 0; nt < 8; nt++) {
            #pragma unroll
            for (int half = 0; half < 2; half++) {
                int r = m0 + wm*32 + mt*16 + g + (half ? 8 : 0);
                int c = n0 + wn*64 + nt*8 + 2*tg;
                float2 v = make_float2(acc[mt][nt][2*half], acc[mt][nt][2*half+1]);
                if (EPI == 0) {
                    *reinterpret_cast<float2*>(C + (size_t)r*N + c) = v;
                } else {
                    int b = r >> 11, s = r & (SEQ-1);
                    int which = c >> 10, rem = c & (DMODEL-1);
                    int h = rem >> 6, d = rem & (HDIM-1);
                    float* dst = (which == 0) ? g_q : (which == 1) ? g_k : g_v;
                    *reinterpret_cast<float2*>(
                        dst + ((size_t)((b*NHEADS + h)*SEQ + s))*HDIM + d) = v;
                }
            }
        }
    }
}

// ============================================================================
// Flash attention (tf32 mma): grid (S/128, B*H), 128 threads (4 warps).
// Each warp: 32 q-rows (2 m-frags sharing K/V frags). Q frags in registers.
// P transposed to A-frags via quad shuffles (no smem round trip).
// 2-stage cp.async KV ring, single barrier per iteration. 2 CTAs/SM.
// ============================================================================
#define SPAD 68
#define AKV_OFF (128*SPAD)              // after Q staging
#define AKVSTG (2*64*SPAD)              // K tile + V tile per stage
#define ATTN_SMEM_BYTES ((128*SPAD + 2*AKVSTG)*4)   // 104448

__device__ __forceinline__ void attn_load_kv(
    float* Ks, float* Vs, size_t hbase, int kt, int tid)
{
    #pragma unroll
    for (int j = 0; j < 8; j++) {
        int id = tid + j*128;
        int r = id >> 4, c4 = (id & 15) * 4;
        size_t off = hbase + (size_t)(kt*64 + r)*HDIM + c4;
        cp16(Ks + r*SPAD + c4, g_k + off);
        cp16(Vs + r*SPAD + c4, g_v + off);
    }
}

__global__ void __launch_bounds__(128, 2)
flashattn()
{
    extern __shared__ float sm[];
    float* Qs = sm;

    const int tid  = threadIdx.x;
    const int lane = tid & 31, warp = tid >> 5;        // 4 warps
    const int g  = lane >> 2, tg = lane & 3;
    const int bh = blockIdx.y;
    const int q0 = blockIdx.x * 128;
    const int rb = warp * 32;                          // warp's 32 q-rows
    const size_t hbase = (size_t)bh * SEQ * HDIM;
    const float scale = 0.125f;

    // prefetch KV tile 0
    attn_load_kv(sm + AKV_OFF, sm + AKV_OFF + 64*SPAD, hbase, 0, tid);
    cp_commit();

    // stage Q (scaled, tf32): 128x64
    #pragma unroll
    for (int j = 0; j < 16; j++) {
        int i  = tid + j*128;
        int r  = i >> 4, c4 = (i & 15) * 4;
        float4 v = *reinterpret_cast<const float4*>(g_q + hbase + (size_t)(q0+r)*HDIM + c4);
        Qs[r*SPAD+c4+0] = f2tf32(v.x * scale);
        Qs[r*SPAD+c4+1] = f2tf32(v.y * scale);
        Qs[r*SPAD+c4+2] = f2tf32(v.z * scale);
        Qs[r*SPAD+c4+3] = f2tf32(v.w * scale);
    }
    __syncthreads();

    // hoist Q fragments to registers (loop-invariant)
    float qf[2][8][4];
    #pragma unroll
    for (int mt = 0; mt < 2; mt++) {
        int rbm = rb + mt*16;
        #pragma unroll
        for (int ks = 0; ks < 8; ks++) {
            int kc = ks*8;
            qf[mt][ks][0] = Qs[(rbm+g  )*SPAD + kc + tg  ];
            qf[mt][ks][1] = Qs[(rbm+g+8)*SPAD + kc + tg  ];
            qf[mt][ks][2] = Qs[(rbm+g  )*SPAD + kc + tg+4];
            qf[mt][ks][3] = Qs[(rbm+g+8)*SPAD + kc + tg+4];
        }
    }

    float mrow[2][2], lrow[2][2];
    #pragma unroll
    for (int mt = 0; mt < 2; mt++) {
        mrow[mt][0] = -1e30f; mrow[mt][1] = -1e30f;
        lrow[mt][0] = 0.f;    lrow[mt][1] = 0.f;
    }
    float o[2][8][4];
    #pragma unroll
    for (int mt = 0; mt < 2; mt++)
        #pragma unroll
        for (int nt = 0; nt < 8; nt++)
            #pragma unroll
            for (int e = 0; e < 4; e++) o[mt][nt][e] = 0.f;

    const int NKT = SEQ/64;
    for (int kt = 0; kt < NKT; kt++) {
        float* Ks = sm + AKV_OFF + (kt & 1)*AKVSTG;
        float* Vs = Ks + 64*SPAD;
        cp_wait<0>();
        __syncthreads();
        if (kt + 1 < NKT) {
            float* Ksn = sm + AKV_OFF + ((kt+1) & 1)*AKVSTG;
            attn_load_kv(Ksn, Ksn + 64*SPAD, hbase, kt+1, tid);
            cp_commit();
        }

        // S = Q @ K^T : warp computes 32 x 64 (K frags shared by both m-frags)
        float sacc[2][8][4];
        #pragma unroll
        for (int mt = 0; mt < 2; mt++)
            #pragma unroll
            for (int nt = 0; nt < 8; nt++)
                #pragma unroll
                for (int e = 0; e < 4; e++) sacc[mt][nt][e] = 0.f;

        #pragma unroll
        for (int ks = 0; ks < 8; ks++) {
            const int kc = ks*8;
            #pragma unroll
            for (int nt = 0; nt < 8; nt++) {
                float bf[2];
                bf[0] = f2tf32(Ks[(nt*8+g)*SPAD + kc + tg  ]);
                bf[1] = f2tf32(Ks[(nt*8+g)*SPAD + kc + tg+4]);
                mma8(sacc[0][nt], qf[0][ks], bf);
                mma8(sacc[1][nt], qf[1][ks], bf);
            }
        }

        // online softmax per m-frag
        #pragma unroll
        for (int mt = 0; mt < 2; mt++) {
            float mx0 = -1e30f, mx1 = -1e30f;
            #pragma unroll
            for (int nt = 0; nt < 8; nt++) {
                mx0 = fmaxf(mx0, fmaxf(sacc[mt][nt][0], sacc[mt][nt][1]));
                mx1 = fmaxf(mx1, fmaxf(sacc[mt][nt][2], sacc[mt][nt][3]));
            }
            mx0 = fmaxf(mx0, __shfl_xor_sync(0xffffffffu, mx0, 1));
            mx0 = fmaxf(mx0, __shfl_xor_sync(0xffffffffu, mx0, 2));
            mx1 = fmaxf(mx1, __shfl_xor_sync(0xffffffffu, mx1, 1));
            mx1 = fmaxf(mx1, __shfl_xor_sync(0xffffffffu, mx1, 2));
            float mn0 = fmaxf(mrow[mt][0], mx0), mn1 = fmaxf(mrow[mt][1], mx1);
            float a0 = __expf(mrow[mt][0] - mn0), a1 = __expf(mrow[mt][1] - mn1);
            float s0 = 0.f, s1 = 0.f;
            #pragma unroll
            for (int nt = 0; nt < 8; nt++) {
                sacc[mt][nt][0] = __expf(sacc[mt][nt][0] - mn0); s0 += sacc[mt][nt][0];
                sacc[mt][nt][1] = __expf(sacc[mt][nt][1] - mn0); s0 += sacc[mt][nt][1];
                sacc[mt][nt][2] = __expf(sacc[mt][nt][2] - mn1); s1 += sacc[mt][nt][2];
                sacc[mt][nt][3] = __expf(sacc[mt][nt][3] - mn1); s1 += sacc[mt][nt][3];
            }
            s0 += __shfl_xor_sync(0xffffffffu, s0, 1);
            s0 += __shfl_xor_sync(0xffffffffu, s0, 2);
            s1 += __shfl_xor_sync(0xffffffffu, s1, 1);
            s1 += __shfl_xor_sync(0xffffffffu, s1, 2);
            lrow[mt][0] = lrow[mt][0]*a0 + s0;
            lrow[mt][1] = lrow[mt][1]*a1 + s1;
            mrow[mt][0] = mn0; mrow[mt][1] = mn1;
            #pragma unroll
            for (int nt = 0; nt < 8; nt++) {
                o[mt][nt][0] *= a0; o[mt][nt][1] *= a0;
                o[mt][nt][2] *= a1; o[mt][nt][3] *= a1;
            }
        }

        // O += P @ V : P A-frags built from sacc via quad shuffles
        const int src0 = (lane & 28) | (tg >> 1);
        const int src1 = src0 | 2;
        #pragma unroll
        for (int ks = 0; ks < 8; ks++) {
            const int kc = ks*8;
            float pa[2][4];
            #pragma unroll
            for (int mt = 0; mt < 2; mt++) {
                float x0 = __shfl_sync(0xffffffffu, sacc[mt][ks][0], src0);
                float x1 = __shfl_sync(0xffffffffu, sacc[mt][ks][1], src0);
                float x2 = __shfl_sync(0xffffffffu, sacc[mt][ks][2], src0);
                float x3 = __shfl_sync(0xffffffffu, sacc[mt][ks][3], src0);
                float y0 = __shfl_sync(0xffffffffu, sacc[mt][ks][0], src1);
                float y1 = __shfl_sync(0xffffffffu, sacc[mt][ks][1], src1);
                float y2 = __shfl_sync(0xffffffffu, sacc[mt][ks][2], src1);
                float y3 = __shfl_sync(0xffffffffu, sacc[mt][ks][3], src1);
                pa[mt][0] = f2tf32((tg & 1) ? x1 : x0);
                pa[mt][1] = f2tf32((tg & 1) ? x3 : x2);
                pa[mt][2] = f2tf32((tg & 1) ? y1 : y0);
                pa[mt][3] = f2tf32((tg & 1) ? y3 : y2);
            }
            #pragma unroll
            for (int nt = 0; nt < 8; nt++) {
                float bf[2];
                bf[0] = f2tf32(Vs[(kc+tg  )*SPAD + nt*8 + g]);
                bf[1] = f2tf32(Vs[(kc+tg+4)*SPAD + nt*8 + g]);
                mma8(o[0][nt], pa[0], bf);
                mma8(o[1][nt], pa[1], bf);
            }
        }
    }

    // epilogue: O /= l ; write to g_attn [B,S,DMODEL]
    const int b = bh / NHEADS, h = bh % NHEADS;
    #pragma unroll
    for (int mt = 0; mt < 2; mt++) {
        float inv0 = 1.f / lrow[mt][0], inv1 = 1.f / lrow[mt][1];
        #pragma unroll
        for (int nt = 0; nt < 8; nt++) {
            int c = h*HDIM + nt*8 + 2*tg;
            size_t base0 = ((size_t)(b*SEQ + q0 + rb + mt*16 + g    ))*DMODEL + c;
            size_t base1 = ((size_t)(b*SEQ + q0 + rb + mt*16 + g + 8))*DMODEL + c;
            *reinterpret_cast<float2*>(g_attn + base0) =
                make_float2(o[mt][nt][0]*inv0, o[mt][nt][1]*inv0);
            *reinterpret_cast<float2*>(g_attn + base1) =
                make_float2(o[mt][nt][2]*inv1, o[mt][nt][3]*inv1);
        }
    }
}

// ============================================================================
extern "C" void kernel_launch(void* const* d_in, const int* in_sizes, int n_in,
                              void* d_out, int out_size)
{
    (void)in_sizes; (void)n_in; (void)out_size;
    const float* x    = (const float*)d_in[0];
    const float* wqkv = (const float*)d_in[1];
    const float* wout = (const float*)d_in[2];
    float* out = (float*)d_out;

    void *xh, *xl, *ah, *al, *wqh, *wql, *woh, *wol, *attn;
    cudaGetSymbolAddress(&xh, g_xh);   cudaGetSymbolAddress(&xl, g_xl);
    cudaGetSymbolAddress(&ah, g_ah);   cudaGetSymbolAddress(&al, g_al);
    cudaGetSymbolAddress(&wqh, g_wqh); cudaGetSymbolAddress(&wql, g_wql);
    cudaGetSymbolAddress(&woh, g_woh); cudaGetSymbolAddress(&wol, g_wol);
    cudaGetSymbolAddress(&attn, g_attn);

    cudaFuncSetAttribute((const void*)gemm_bf3<1>,
                         cudaFuncAttributeMaxDynamicSharedMemorySize, GEMM_SMEM_BYTES);
    cudaFuncSetAttribute((const void*)gemm_bf3<0>,
                         cudaFuncAttributeMaxDynamicSharedMemorySize, GEMM_SMEM_BYTES);
    cudaFuncSetAttribute((const void*)flashattn,
                         cudaFuncAttributeMaxDynamicSharedMemorySize, ATTN_SMEM_BYTES);

    // prep: split x; split+transpose weights
    split_plain<<<(MTOT*DMODEL/4 + 255)/256, 256>>>(x, (bf16*)xh, (bf16*)xl, MTOT*DMODEL/4);
    split_T<<<dim3(3*DMODEL/32, DMODEL/32), 256>>>(wqkv, (bf16*)wqh, (bf16*)wql, DMODEL, 3*DMODEL);
    split_T<<<dim3(DMODEL/32, DMODEL/32), 256>>>(wout, (bf16*)woh, (bf16*)wol, DMODEL, DMODEL);

    // 1) QKV projection -> scatter to g_q/g_k/g_v
    gemm_bf3<1><<<dim3(3*DMODEL/128, MTOT/128), 256, GEMM_SMEM_BYTES>>>(
        (const bf16*)xh, (const bf16*)xl, (const bf16*)wqh, (const bf16*)wql,
        nullptr, MTOT, 3*DMODEL, DMODEL);

    // 2) flash attention -> g_attn [B,S,D]
    flashattn<<<dim3(SEQ/128, BATCH*NHEADS), 128, ATTN_SMEM_BYTES>>>();

    // prep: split attention output
    split_plain<<<(MTOT*DMODEL/4 + 255)/256, 256>>>((const float*)attn, (bf16*)ah, (bf16*)al,
                                                    MTOT*DMODEL/4);

    // 3) out projection -> d_out
    gemm_bf3<0><<<dim3(DMODEL/128, MTOT/128), 256, GEMM_SMEM_BYTES>>>(
        (const bf16*)ah, (const bf16*)al, (const bf16*)woh, (const bf16*)wol,
        out, MTOT, DMODEL, DMODEL);
}